// round 2
// baseline (speedup 1.0000x reference)
#include <cuda_runtime.h>

#define NNODES 100000
#define NF4 (NNODES * 16)

// Scratch (device globals — no allocs allowed)
__device__ float4 g_y[NF4];     // transformed neighbor features (l-path)
__device__ float4 g_r[NF4];     // root-path features
__device__ float4 g_agg[NF4];   // scatter accumulator
__device__ float4 g_h[NF4];     // hidden activations
__device__ float  g_deg[NNODES];

// ---------- packed f32x2 helpers (sm_100+) ----------
static __device__ __forceinline__ unsigned long long pk2(float a, float b) {
    unsigned long long r;
    asm("mov.b64 %0, {%1, %2};" : "=l"(r) : "f"(a), "f"(b));
    return r;
}
static __device__ __forceinline__ void ffma2(unsigned long long& d,
                                             unsigned long long a,
                                             unsigned long long b) {
    asm("fma.rn.f32x2 %0, %1, %2, %0;" : "+l"(d) : "l"(a), "l"(b));
}
static __device__ __forceinline__ float2 upk(unsigned long long v) {
    float2 r;
    asm("mov.b64 {%0, %1}, %2;" : "=f"(r.x), "=f"(r.y) : "l"(v));
    return r;
}

// ---------- utility kernels ----------
__global__ void zero_k(float4* __restrict__ p, int n) {
    int i = blockIdx.x * blockDim.x + threadIdx.x;
    if (i < n) p[i] = make_float4(0.f, 0.f, 0.f, 0.f);
}

__global__ void deg_k(const int* __restrict__ dst, float* __restrict__ deg, int E) {
    int e = blockIdx.x * blockDim.x + threadIdx.x;
    if (e < E) atomicAdd(&deg[dst[e]], 1.0f);
}

// ---------- dual GEMM: Yl = X@Wl, Yr = X@Wr   (X: [nrows,K], W: [K,64]) ----------
// 64 rows per block, 256 threads: col = tid&63, 16 rows per thread.
// Transposed smem tile with stride 68 (4-float pad): coalesced global loads,
// <=4-way STS conflict, 16B-aligned broadcast LDS.128 in the mainloop.
template <int K>
__global__ __launch_bounds__(256) void gemm_dual(
    const float* __restrict__ X,
    const float* __restrict__ Wl, const float* __restrict__ Wr,
    float* __restrict__ Yl, float* __restrict__ Yr, int nrows) {
    __shared__ float xsT[K * 68];
    int n0 = blockIdx.x * 64;
    for (int i = threadIdx.x; i < 64 * K; i += 256) {
        int r = i / K, k = i - r * K;
        float v = (n0 + r < nrows) ? X[(size_t)(n0 + r) * K + k] : 0.f;
        xsT[k * 68 + r] = v;
    }
    __syncthreads();

    int col = threadIdx.x & 63;
    int rb  = (threadIdx.x >> 6) * 16;  // 16 rows per thread
    unsigned long long accl[8] = {}, accr[8] = {};

    for (int k = 0; k < K; k++) {
        float wl = Wl[k * 64 + col];
        float wr = Wr[k * 64 + col];
        unsigned long long wl2 = pk2(wl, wl);
        unsigned long long wr2 = pk2(wr, wr);
        const ulonglong2* ap = reinterpret_cast<const ulonglong2*>(&xsT[k * 68 + rb]);
#pragma unroll
        for (int q = 0; q < 4; q++) {
            ulonglong2 a = ap[q];   // rows rb+4q .. rb+4q+3 (two f32x2 pairs)
            ffma2(accl[2 * q],     a.x, wl2);
            ffma2(accr[2 * q],     a.x, wr2);
            ffma2(accl[2 * q + 1], a.y, wl2);
            ffma2(accr[2 * q + 1], a.y, wr2);
        }
    }

#pragma unroll
    for (int p = 0; p < 8; p++) {
        int row = n0 + rb + 2 * p;
        float2 l = upk(accl[p]);
        float2 r = upk(accr[p]);
        if (row < nrows) {
            Yl[(size_t)row * 64 + col] = l.x;
            Yr[(size_t)row * 64 + col] = r.x;
        }
        if (row + 1 < nrows) {
            Yl[(size_t)(row + 1) * 64 + col] = l.y;
            Yr[(size_t)(row + 1) * 64 + col] = r.y;
        }
    }
}

// ---------- edge scatter: agg[dst] += y[src], 64 floats as 16 float4 ----------
__global__ void scat_k(const int* __restrict__ src, const int* __restrict__ dst,
                       const float4* __restrict__ y, float4* __restrict__ agg, int E) {
    int idx = blockIdx.x * blockDim.x + threadIdx.x;
    if (idx >= E * 16) return;
    int e = idx >> 4, c = idx & 15;
    int s = src[e], d = dst[e];
    float4 v = y[(size_t)s * 16 + c];
    atomicAdd(&agg[(size_t)d * 16 + c], v);   // vector red (sm_90+)
}

// ---------- finalize layer: h = relu(agg/max(deg,1) + b + r) ----------
__global__ void fin_k(const float4* __restrict__ agg, const float4* __restrict__ r,
                      const float* __restrict__ deg, const float* __restrict__ b,
                      float4* __restrict__ h, int n4) {
    int i = blockIdx.x * blockDim.x + threadIdx.x;
    if (i >= n4) return;
    int node = i >> 4, c = i & 15;
    float inv = 1.f / fmaxf(deg[node], 1.f);
    float4 a = agg[i], rr = r[i];
    float4 bb = reinterpret_cast<const float4*>(b)[c];
    float4 o;
    o.x = fmaxf(fmaf(a.x, inv, bb.x + rr.x), 0.f);
    o.y = fmaxf(fmaf(a.y, inv, bb.y + rr.y), 0.f);
    o.z = fmaxf(fmaf(a.z, inv, bb.z + rr.z), 0.f);
    o.w = fmaxf(fmaf(a.w, inv, bb.w + rr.w), 0.f);
    h[i] = o;
}

// ---------- fused finalize layer2 + classifier: out = relu(...) @ Wc + bc ----------
__global__ void fin2_k(const float* __restrict__ agg, const float* __restrict__ r,
                       const float* __restrict__ deg, const float* __restrict__ b,
                       const float* __restrict__ Wc, const float* __restrict__ bc,
                       float* __restrict__ out, int n) {
    int t = blockIdx.x * blockDim.x + threadIdx.x;
    int node = t >> 5, lane = t & 31;
    if (node >= n) return;
    float inv = 1.f / fmaxf(deg[node], 1.f);
    float a0 = 0.f, a1 = 0.f;
#pragma unroll
    for (int q = 0; q < 2; q++) {
        int j = lane + q * 32;
        float hv = fmaxf(fmaf(agg[(size_t)node * 64 + j], inv,
                              b[j] + r[(size_t)node * 64 + j]), 0.f);
        a0 = fmaf(hv, Wc[2 * j], a0);
        a1 = fmaf(hv, Wc[2 * j + 1], a1);
    }
#pragma unroll
    for (int o = 16; o; o >>= 1) {
        a0 += __shfl_xor_sync(0xffffffffu, a0, o);
        a1 += __shfl_xor_sync(0xffffffffu, a1, o);
    }
    if (lane == 0) {
        out[node * 2]     = a0 + bc[0];
        out[node * 2 + 1] = a1 + bc[1];
    }
}

extern "C" void kernel_launch(void* const* d_in, const int* in_sizes, int n_in,
                              void* d_out, int out_size) {
    const float* x   = (const float*)d_in[0];
    const int*   ei  = (const int*)d_in[1];
    const float* W1l = (const float*)d_in[2];
    const float* b1  = (const float*)d_in[3];
    const float* W1r = (const float*)d_in[4];
    const float* W2l = (const float*)d_in[5];
    const float* b2  = (const float*)d_in[6];
    const float* W2r = (const float*)d_in[7];
    const float* Wc  = (const float*)d_in[8];
    const float* bc  = (const float*)d_in[9];
    float* out = (float*)d_out;

    const int N = in_sizes[0] / 165;
    const int E = in_sizes[1] / 2;
    const int* src = ei;
    const int* dst = ei + E;

    float4 *yp, *rp, *aggp, *hp;
    float* degp;
    cudaGetSymbolAddress((void**)&yp,   g_y);
    cudaGetSymbolAddress((void**)&rp,   g_r);
    cudaGetSymbolAddress((void**)&aggp, g_agg);
    cudaGetSymbolAddress((void**)&hp,   g_h);
    cudaGetSymbolAddress((void**)&degp, g_deg);

    const int n4 = N * 16;
    const int TB = 256;

    // degree (shared by both layers)
    zero_k<<<(N / 4 + TB - 1) / TB, TB>>>((float4*)degp, N / 4);
    deg_k<<<(E + TB - 1) / TB, TB>>>(dst, degp, E);

    // ---- layer 1 ----
    zero_k<<<(n4 + TB - 1) / TB, TB>>>(aggp, n4);
    gemm_dual<165><<<(N + 63) / 64, TB>>>(x, W1l, W1r, (float*)yp, (float*)rp, N);
    scat_k<<<((size_t)E * 16 + TB - 1) / TB, TB>>>(src, dst, yp, aggp, E);
    fin_k<<<(n4 + TB - 1) / TB, TB>>>(aggp, rp, degp, b1, hp, n4);

    // ---- layer 2 ----
    zero_k<<<(n4 + TB - 1) / TB, TB>>>(aggp, n4);
    gemm_dual<64><<<(N + 63) / 64, TB>>>((const float*)hp, W2l, W2r,
                                         (float*)yp, (float*)rp, N);
    scat_k<<<((size_t)E * 16 + TB - 1) / TB, TB>>>(src, dst, yp, aggp, E);

    // ---- finalize + classifier ----
    fin2_k<<<((size_t)N * 32 + TB - 1) / TB, TB>>>((const float*)aggp, (const float*)rp,
                                                   degp, b2, Wc, bc, out, N);
}